// round 6
// baseline (speedup 1.0000x reference)
#include <cuda_runtime.h>
#include <math.h>
#include <stdint.h>

// ---------------- problem constants ----------------
#define HID 2048
#define NEXP 256
#define NGRP 8
#define TOPG 4
#define TOPK 8
#define RSCALE 2.5f
#define MT 64                  // tokens per CTA
#define KT 32                  // K per smem stage
#define NST (HID / KT)         // 64 stages

// ---------------- smem layout (raw fp32 tiles, 3-stage) ----------------
// row stride 36 floats: bank = (4*row + col) & 31 -> conflict-free frag loads
#define RS 36
#define OFF_BIAS 0
#define OFF_TILES 1024
#define AOFF 0
#define BOFF (MT * RS * 4)                       // 9216
#define STAGE (MT * RS * 4 + NEXP * RS * 4)      // 46080
#define SMEM_TOTAL (OFF_TILES + 3 * STAGE)       // 139264
#define SC_STRIDE 260

#define MMA(d, a, b) asm volatile( \
    "mma.sync.aligned.m16n8k8.row.col.f32.tf32.tf32.f32 " \
    "{%0,%1,%2,%3},{%4,%5,%6,%7},{%8,%9},{%0,%1,%2,%3};" \
    : "+f"((d)[0]), "+f"((d)[1]), "+f"((d)[2]), "+f"((d)[3]) \
    : "r"((a)[0]), "r"((a)[1]), "r"((a)[2]), "r"((a)[3]), \
      "r"((b)[0]), "r"((b)[1]))

#define CPA(dst, src) asm volatile( \
    "cp.async.cg.shared.global [%0], [%1], 16;" :: "r"(dst), "l"(src) : "memory")
#define CPA_COMMIT asm volatile("cp.async.commit_group;" ::: "memory")

static __device__ __forceinline__ uint32_t s2u(const void* p) {
    uint32_t r;
    asm("{ .reg .u64 t; cvta.to.shared.u64 t, %1; cvt.u32.u64 %0, t; }" : "=r"(r) : "l"(p));
    return r;
}

// round-to-nearest tf32 split: v ~= hi + lo, both exactly tf32
static __device__ __forceinline__ void split2(float v, uint32_t& h, uint32_t& l) {
    asm("cvt.rna.tf32.f32 %0, %1;" : "=r"(h) : "f"(v));
    float r = v - __uint_as_float(h);
    asm("cvt.rna.tf32.f32 %0, %1;" : "=r"(l) : "f"(r));
}

// ---------------------------------------------------------------------------
// Fused: 3xTF32 mma.sync GEMM (64 x 256 x 2048 per CTA), dual accumulators,
// term-major MMA ordering (no same-acc back-to-back), 3-stage cp.async,
// one barrier per stage + sigmoid + grouped top-k routing.
// 512 threads, 16 warps, 32x32 warp tiles.
// ---------------------------------------------------------------------------
extern "C" __global__ void __launch_bounds__(512, 1)
gate_fused_kernel(const float* __restrict__ x,
                  const float* __restrict__ w,
                  const float* __restrict__ bias,
                  float* __restrict__ out, int N, int with_idx)
{
    extern __shared__ __align__(1024) char smem[];
    const uint32_t sb = s2u(smem);
    const int tid  = threadIdx.x;
    const int wid  = tid >> 5;
    const int lane = tid & 31;
    const int m0   = blockIdx.x * MT;
    const int wm   = wid & 1;      // 2 M-groups of 32 tokens
    const int wn   = wid >> 1;     // 8 N-groups of 32 experts

    float* bs = (float*)(smem + OFF_BIAS);
    if (tid < NEXP) bs[tid] = bias[tid];

    float accH[2][4][4], accL[2][4][4];
    #pragma unroll
    for (int i = 0; i < 2; i++)
        #pragma unroll
        for (int j = 0; j < 4; j++)
            #pragma unroll
            for (int c = 0; c < 4; c++) { accH[i][j][c] = 0.0f; accL[i][j][c] = 0.0f; }

    const int lrow = tid >> 3;       // 0..63
    const int lq   = tid & 7;

    // ---- async load of raw fp32 tiles for stage s (buffer s % 3) ----
    auto ldga = [&](int s) {
        const int k0 = s * KT;
        const uint32_t bufa = sb + OFF_TILES + (s % 3) * STAGE;
        {   // A: 64 rows, 1 float4 per thread
            uint32_t dst = bufa + AOFF + (uint32_t)(lrow * RS + lq * 4) * 4;
            CPA(dst, x + (size_t)(m0 + lrow) * HID + k0 + lq * 4);
        }
        #pragma unroll
        for (int i = 0; i < 4; i++) {   // B: 256 rows, 4 float4 per thread
            int row = lrow + i * 64;
            uint32_t dst = bufa + BOFF + (uint32_t)(row * RS + lq * 4) * 4;
            CPA(dst, w + (size_t)row * HID + k0 + lq * 4);
        }
        CPA_COMMIT;
    };

    const int afo = (wm * 32 + (lane >> 2)) * RS + (lane & 3);
    const int bfo = (wn * 32 + (lane >> 2)) * RS + (lane & 3);

    auto compute = [&](int s) {
        const char* buf = smem + OFF_TILES + (s % 3) * STAGE;
        const float* Ar = (const float*)(buf + AOFF);
        const float* Br = (const float*)(buf + BOFF);
        #pragma unroll
        for (int ks = 0; ks < 4; ks++) {
            const int kb = ks * 8;
            // A frags: split once per ks, shared across both ni halves
            uint32_t ah[2][4], al[2][4];
            #pragma unroll
            for (int mi = 0; mi < 2; mi++) {
                int o = afo + mi * (16 * RS) + kb;
                split2(Ar[o],              ah[mi][0], al[mi][0]);
                split2(Ar[o + 8 * RS],     ah[mi][1], al[mi][1]);
                split2(Ar[o + 4],          ah[mi][2], al[mi][2]);
                split2(Ar[o + 8 * RS + 4], ah[mi][3], al[mi][3]);
            }
            #pragma unroll
            for (int h = 0; h < 2; h++) {
                uint32_t bh[2][2], bl[2][2];
                #pragma unroll
                for (int n2 = 0; n2 < 2; n2++) {
                    int o = bfo + (h * 2 + n2) * (8 * RS) + kb;
                    split2(Br[o],     bh[n2][0], bl[n2][0]);
                    split2(Br[o + 4], bh[n2][1], bl[n2][1]);
                }
                // term-major ordering: no same-accumulator back-to-back MMAs
                #pragma unroll
                for (int mi = 0; mi < 2; mi++)
                    #pragma unroll
                    for (int n2 = 0; n2 < 2; n2++)
                        MMA(accH[mi][h * 2 + n2], ah[mi], bh[n2]);
                #pragma unroll
                for (int mi = 0; mi < 2; mi++)
                    #pragma unroll
                    for (int n2 = 0; n2 < 2; n2++)
                        MMA(accL[mi][h * 2 + n2], al[mi], bh[n2]);
                #pragma unroll
                for (int mi = 0; mi < 2; mi++)
                    #pragma unroll
                    for (int n2 = 0; n2 < 2; n2++)
                        MMA(accL[mi][h * 2 + n2], ah[mi], bl[n2]);
            }
        }
    };

    // ---- 3-stage pipelined main loop, one barrier per stage ----
    ldga(0); ldga(1);
    for (int s = 0; s < NST; s++) {
        if (s < NST - 1) {
            asm volatile("cp.async.wait_group 1;" ::: "memory");
        } else {
            asm volatile("cp.async.wait_group 0;" ::: "memory");
        }
        __syncthreads();
        if (s + 2 < NST) ldga(s + 2);
        compute(s);
    }
    __syncthreads();   // tiles dead; reuse smem for scores overlay

    // ---- epilogue: combine acc, +bias, sigmoid, scores overlay ----
    float* sc = (float*)(smem + OFF_TILES);
    #pragma unroll
    for (int mi = 0; mi < 2; mi++) {
        int tr = wm * 32 + mi * 16 + (lane >> 2);
        #pragma unroll
        for (int ni = 0; ni < 4; ni++) {
            int e = wn * 32 + ni * 8 + (lane & 3) * 2;
            float s0 = (accH[mi][ni][0] + accL[mi][ni][0]) + bs[e];
            float s1 = (accH[mi][ni][1] + accL[mi][ni][1]) + bs[e + 1];
            float s2 = (accH[mi][ni][2] + accL[mi][ni][2]) + bs[e];
            float s3 = (accH[mi][ni][3] + accL[mi][ni][3]) + bs[e + 1];
            float2 v0, v1;
            v0.x = 1.0f / (1.0f + expf(-s0));
            v0.y = 1.0f / (1.0f + expf(-s1));
            v1.x = 1.0f / (1.0f + expf(-s2));
            v1.y = 1.0f / (1.0f + expf(-s3));
            *(float2*)&sc[tr * SC_STRIDE + e]       = v0;
            *(float2*)&sc[(tr + 8) * SC_STRIDE + e] = v1;
        }
    }
    __syncthreads();

    // ---- routing: warp per token, 4 tokens per warp ----
    for (int it = 0; it < 4; it++) {
        const int t = wid * 4 + it;
        const float* row = sc + t * SC_STRIDE;

        float orig[NGRP], rsc[NGRP];
        #pragma unroll
        for (int s = 0; s < NGRP; s++) {
            float sg = row[s * 32 + lane];
            orig[s] = sg;
            rsc[s] = sg + bs[s * 32 + lane];
        }

        // group score = top-2 sum (ties -> lower expert index)
        float gs[NGRP];
        #pragma unroll
        for (int g = 0; g < NGRP; g++) {
            float m1 = rsc[g];
            int l1 = lane;
            #pragma unroll
            for (int off = 16; off >= 1; off >>= 1) {
                float ov = __shfl_xor_sync(0xffffffffu, m1, off);
                int ol = __shfl_xor_sync(0xffffffffu, l1, off);
                if (ov > m1 || (ov == m1 && ol < l1)) { m1 = ov; l1 = ol; }
            }
            float v2 = (lane == l1) ? -INFINITY : rsc[g];
            #pragma unroll
            for (int off = 16; off >= 1; off >>= 1)
                v2 = fmaxf(v2, __shfl_xor_sync(0xffffffffu, v2, off));
            gs[g] = m1 + v2;
        }

        // keep top-4 groups (ties -> lower group index)
        float mv[NGRP];
        #pragma unroll
        for (int g = 0; g < NGRP; g++) {
            int cnt = 0;
            #pragma unroll
            for (int h = 0; h < NGRP; h++)
                cnt += (gs[h] > gs[g]) || (gs[h] == gs[g] && h < g);
            mv[g] = (cnt < TOPG) ? rsc[g] : -INFINITY;
        }

        // iterative top-8 (ties -> lower expert index)
        float wsel[TOPK];
        int esel[TOPK];
        #pragma unroll
        for (int k = 0; k < TOPK; k++) {
            float bv2 = -INFINITY; int be = NEXP; float bo = 0.0f;
            #pragma unroll
            for (int s = 0; s < NGRP; s++)
                if (mv[s] > bv2) { bv2 = mv[s]; be = s * 32 + lane; bo = orig[s]; }
            #pragma unroll
            for (int off = 16; off >= 1; off >>= 1) {
                float ov = __shfl_xor_sync(0xffffffffu, bv2, off);
                int oe = __shfl_xor_sync(0xffffffffu, be, off);
                float oo = __shfl_xor_sync(0xffffffffu, bo, off);
                if (ov > bv2 || (ov == bv2 && oe < be)) { bv2 = ov; be = oe; bo = oo; }
            }
            wsel[k] = bo;
            esel[k] = be;
            if ((be & 31) == lane) {
                int bslot = be >> 5;
                #pragma unroll
                for (int s = 0; s < NGRP; s++)
                    if (s == bslot) mv[s] = -INFINITY;
            }
        }

        float tot = 0.0f;
        #pragma unroll
        for (int k = 0; k < TOPK; k++) tot += wsel[k];
        float inv = RSCALE / tot;

        const int gt = m0 + t;
        #pragma unroll
        for (int k = 0; k < TOPK; k++) {
            if (lane == k) {
                out[(size_t)gt * TOPK + k] = wsel[k] * inv;
                if (with_idx)
                    out[(size_t)N * TOPK + (size_t)gt * TOPK + k] = (float)esel[k];
            }
        }
    }
}

// ---------------------------------------------------------------------------
extern "C" void kernel_launch(void* const* d_in, const int* in_sizes, int n_in,
                              void* d_out, int out_size)
{
    const float* x    = (const float*)d_in[0];
    const float* w    = (const float*)d_in[1];
    const float* bias = (const float*)d_in[2];
    float* out = (float*)d_out;

    int N = in_sizes[0] / HID;
    int with_idx = (out_size >= 2 * N * TOPK) ? 1 : 0;

    cudaFuncSetAttribute(gate_fused_kernel,
                         cudaFuncAttributeMaxDynamicSharedMemorySize, SMEM_TOTAL);
    gate_fused_kernel<<<N / MT, 512, SMEM_TOTAL>>>(x, w, bias, out, N, with_idx);
}

// round 7
// speedup vs baseline: 1.0161x; 1.0161x over previous
#include <cuda_runtime.h>
#include <math.h>
#include <stdint.h>

// ---------------- problem constants ----------------
#define HID 2048
#define NEXP 256
#define NGRP 8
#define TOPG 4
#define TOPK 8
#define RSCALE 2.5f
#define MT 64                  // tokens per CTA
#define KT 32                  // K per smem stage
#define NST (HID / KT)         // 64 stages

// ---------------- smem layout ----------------
// row stride 36 floats: bank = (4*row + col) & 31 -> conflict-free frag loads
#define RS 36
#define OFF_BIAS 0
#define OFF_TILES 1024
#define AOFF 0
#define BOFF (MT * RS * 4)                       // 9216
#define STAGE (MT * RS * 4 + NEXP * RS * 4)      // 46080
#define NBUF 3
#define OFF_LO (OFF_TILES + NBUF * STAGE)        // 139264 (single lo buffer)
#define SMEM_TOTAL (OFF_LO + STAGE)              // 185344
#define SC_STRIDE 260

#define MMA(d, a, b) asm volatile( \
    "mma.sync.aligned.m16n8k8.row.col.f32.tf32.tf32.f32 " \
    "{%0,%1,%2,%3},{%4,%5,%6,%7},{%8,%9},{%0,%1,%2,%3};" \
    : "+f"((d)[0]), "+f"((d)[1]), "+f"((d)[2]), "+f"((d)[3]) \
    : "r"((a)[0]), "r"((a)[1]), "r"((a)[2]), "r"((a)[3]), \
      "r"((b)[0]), "r"((b)[1]))

#define CPA(dst, src) asm volatile( \
    "cp.async.cg.shared.global [%0], [%1], 16;" :: "r"(dst), "l"(src) : "memory")
#define CPA_COMMIT asm volatile("cp.async.commit_group;" ::: "memory")

static __device__ __forceinline__ uint32_t s2u(const void* p) {
    uint32_t r;
    asm("{ .reg .u64 t; cvta.to.shared.u64 t, %1; cvt.u32.u64 %0, t; }" : "=r"(r) : "l"(p));
    return r;
}

// truncation split: hi = v with low 13 mantissa bits zeroed (exactly the bits
// the tf32 HMMA datapath keeps), lo = v - hi (exact in fp32).
static __device__ __forceinline__ void tsplit(uint32_t v, uint32_t& h, uint32_t& l) {
    h = v & 0xFFFFE000u;
    l = __float_as_uint(__uint_as_float(v) - __uint_as_float(h));
}

// ---------------------------------------------------------------------------
// Fused: 3xTF32 mma.sync GEMM (64 x 256 x 2048 per CTA), dual accumulators,
// split-once-per-element in smem (in-place hi + lo tile), 3-buffer cp.async
// pipeline + sigmoid + grouped top-k routing. 512 threads, 32x32 warp tiles.
// ---------------------------------------------------------------------------
extern "C" __global__ void __launch_bounds__(512, 1)
gate_fused_kernel(const float* __restrict__ x,
                  const float* __restrict__ w,
                  const float* __restrict__ bias,
                  float* __restrict__ out, int N, int with_idx)
{
    extern __shared__ __align__(1024) char smem[];
    const uint32_t sb = s2u(smem);
    const int tid  = threadIdx.x;
    const int wid  = tid >> 5;
    const int lane = tid & 31;
    const int m0   = blockIdx.x * MT;
    const int wm   = wid & 1;      // 2 M-groups of 32 tokens
    const int wn   = wid >> 1;     // 8 N-groups of 32 experts

    float* bs = (float*)(smem + OFF_BIAS);
    if (tid < NEXP) bs[tid] = bias[tid];

    float accH[2][4][4], accL[2][4][4];
    #pragma unroll
    for (int i = 0; i < 2; i++)
        #pragma unroll
        for (int j = 0; j < 4; j++)
            #pragma unroll
            for (int c = 0; c < 4; c++) { accH[i][j][c] = 0.0f; accL[i][j][c] = 0.0f; }

    const int lrow = tid >> 3;       // 0..63
    const int lq   = tid & 7;
    const uint32_t tof = (uint32_t)(lrow * RS + lq * 4) * 4;  // thread tile offset

    // ---- async load of raw fp32 tiles for stage s (buffer s % 3) ----
    auto ldga = [&](int s) {
        const int k0 = s * KT;
        const uint32_t bufa = sb + OFF_TILES + (s % NBUF) * STAGE;
        CPA(bufa + AOFF + tof, x + (size_t)(m0 + lrow) * HID + k0 + lq * 4);
        #pragma unroll
        for (int i = 0; i < 4; i++) {
            int row = lrow + i * 64;
            uint32_t dst = bufa + BOFF + (uint32_t)(row * RS + lq * 4) * 4;
            CPA(dst, w + (size_t)row * HID + k0 + lq * 4);
        }
        CPA_COMMIT;
    };

    // ---- split pass: mask buf in place (-> hi) and emit lo tile ----
    auto split_pass = [&](int s) {
        char* buf = smem + OFF_TILES + (s % NBUF) * STAGE;
        char* lob = smem + OFF_LO;
        {
            uint4 v = *(uint4*)(buf + AOFF + tof);
            uint4 h, l;
            tsplit(v.x, h.x, l.x); tsplit(v.y, h.y, l.y);
            tsplit(v.z, h.z, l.z); tsplit(v.w, h.w, l.w);
            *(uint4*)(buf + AOFF + tof) = h;
            *(uint4*)(lob + AOFF + tof) = l;
        }
        #pragma unroll
        for (int i = 0; i < 4; i++) {
            uint32_t o = BOFF + (uint32_t)((lrow + i * 64) * RS + lq * 4) * 4;
            uint4 v = *(uint4*)(buf + o);
            uint4 h, l;
            tsplit(v.x, h.x, l.x); tsplit(v.y, h.y, l.y);
            tsplit(v.z, h.z, l.z); tsplit(v.w, h.w, l.w);
            *(uint4*)(buf + o) = h;
            *(uint4*)(lob + o) = l;
        }
    };

    const int afo = (wm * 32 + (lane >> 2)) * RS + (lane & 3);
    const int bfo = (wn * 32 + (lane >> 2)) * RS + (lane & 3);

    auto compute = [&](int s) {
        const char* buf = smem + OFF_TILES + (s % NBUF) * STAGE;
        const float* Ah = (const float*)(buf + AOFF);
        const float* Bh = (const float*)(buf + BOFF);
        const float* Al = (const float*)(smem + OFF_LO + AOFF);
        const float* Bl = (const float*)(smem + OFF_LO + BOFF);
        #pragma unroll
        for (int ks = 0; ks < 4; ks++) {
            const int kb = ks * 8;
            uint32_t ah[2][4], al[2][4];
            #pragma unroll
            for (int mi = 0; mi < 2; mi++) {
                int o = afo + mi * (16 * RS) + kb;
                ah[mi][0] = __float_as_uint(Ah[o]);
                ah[mi][1] = __float_as_uint(Ah[o + 8 * RS]);
                ah[mi][2] = __float_as_uint(Ah[o + 4]);
                ah[mi][3] = __float_as_uint(Ah[o + 8 * RS + 4]);
                al[mi][0] = __float_as_uint(Al[o]);
                al[mi][1] = __float_as_uint(Al[o + 8 * RS]);
                al[mi][2] = __float_as_uint(Al[o + 4]);
                al[mi][3] = __float_as_uint(Al[o + 8 * RS + 4]);
            }
            #pragma unroll
            for (int h = 0; h < 2; h++) {
                uint32_t bh[2][2], bl[2][2];
                #pragma unroll
                for (int n2 = 0; n2 < 2; n2++) {
                    int o = bfo + (h * 2 + n2) * (8 * RS) + kb;
                    bh[n2][0] = __float_as_uint(Bh[o]);
                    bh[n2][1] = __float_as_uint(Bh[o + 4]);
                    bl[n2][0] = __float_as_uint(Bl[o]);
                    bl[n2][1] = __float_as_uint(Bl[o + 4]);
                }
                #pragma unroll
                for (int mi = 0; mi < 2; mi++)
                    #pragma unroll
                    for (int n2 = 0; n2 < 2; n2++) {
                        MMA(accH[mi][h * 2 + n2], ah[mi], bh[n2]);  // exact products
                        MMA(accL[mi][h * 2 + n2], al[mi], bh[n2]);
                        MMA(accL[mi][h * 2 + n2], ah[mi], bl[n2]);
                    }
            }
        }
    };

    // ---- pipelined main loop (3 raw buffers, single lo buffer) ----
    ldga(0); ldga(1);
    for (int s = 0; s < NST; s++) {
        if (s + 1 < NST) {
            asm volatile("cp.async.wait_group 1;" ::: "memory");
        } else {
            asm volatile("cp.async.wait_group 0;" ::: "memory");
        }
        __syncthreads();                 // buf[s] complete; compute(s-1) done everywhere
        if (s + 2 < NST) ldga(s + 2);    // safe: targets buf[(s+2)%3] (dead since s-1)
        split_pass(s);
        __syncthreads();                 // hi/lo tiles ready
        compute(s);
    }
    __syncthreads();   // tiles dead; reuse smem for scores overlay

    // ---- epilogue: combine acc, +bias, sigmoid, scores overlay ----
    float* sc = (float*)(smem + OFF_TILES);
    #pragma unroll
    for (int mi = 0; mi < 2; mi++) {
        int tr = wm * 32 + mi * 16 + (lane >> 2);
        #pragma unroll
        for (int ni = 0; ni < 4; ni++) {
            int e = wn * 32 + ni * 8 + (lane & 3) * 2;
            float s0 = (accH[mi][ni][0] + accL[mi][ni][0]) + bs[e];
            float s1 = (accH[mi][ni][1] + accL[mi][ni][1]) + bs[e + 1];
            float s2 = (accH[mi][ni][2] + accL[mi][ni][2]) + bs[e];
            float s3 = (accH[mi][ni][3] + accL[mi][ni][3]) + bs[e + 1];
            float2 v0, v1;
            v0.x = 1.0f / (1.0f + expf(-s0));
            v0.y = 1.0f / (1.0f + expf(-s1));
            v1.x = 1.0f / (1.0f + expf(-s2));
            v1.y = 1.0f / (1.0f + expf(-s3));
            *(float2*)&sc[tr * SC_STRIDE + e]       = v0;
            *(float2*)&sc[(tr + 8) * SC_STRIDE + e] = v1;
        }
    }
    __syncthreads();

    // ---- routing: warp per token, 4 tokens per warp ----
    for (int it = 0; it < 4; it++) {
        const int t = wid * 4 + it;
        const float* row = sc + t * SC_STRIDE;

        float orig[NGRP], rsc[NGRP];
        #pragma unroll
        for (int s = 0; s < NGRP; s++) {
            float sg = row[s * 32 + lane];
            orig[s] = sg;
            rsc[s] = sg + bs[s * 32 + lane];
        }

        // group score = top-2 sum (ties -> lower expert index)
        float gs[NGRP];
        #pragma unroll
        for (int g = 0; g < NGRP; g++) {
            float m1 = rsc[g];
            int l1 = lane;
            #pragma unroll
            for (int off = 16; off >= 1; off >>= 1) {
                float ov = __shfl_xor_sync(0xffffffffu, m1, off);
                int ol = __shfl_xor_sync(0xffffffffu, l1, off);
                if (ov > m1 || (ov == m1 && ol < l1)) { m1 = ov; l1 = ol; }
            }
            float v2 = (lane == l1) ? -INFINITY : rsc[g];
            #pragma unroll
            for (int off = 16; off >= 1; off >>= 1)
                v2 = fmaxf(v2, __shfl_xor_sync(0xffffffffu, v2, off));
            gs[g] = m1 + v2;
        }

        // keep top-4 groups (ties -> lower group index)
        float mv[NGRP];
        #pragma unroll
        for (int g = 0; g < NGRP; g++) {
            int cnt = 0;
            #pragma unroll
            for (int h = 0; h < NGRP; h++)
                cnt += (gs[h] > gs[g]) || (gs[h] == gs[g] && h < g);
            mv[g] = (cnt < TOPG) ? rsc[g] : -INFINITY;
        }

        // iterative top-8 (ties -> lower expert index)
        float wsel[TOPK];
        int esel[TOPK];
        #pragma unroll
        for (int k = 0; k < TOPK; k++) {
            float bv2 = -INFINITY; int be = NEXP; float bo = 0.0f;
            #pragma unroll
            for (int s = 0; s < NGRP; s++)
                if (mv[s] > bv2) { bv2 = mv[s]; be = s * 32 + lane; bo = orig[s]; }
            #pragma unroll
            for (int off = 16; off >= 1; off >>= 1) {
                float ov = __shfl_xor_sync(0xffffffffu, bv2, off);
                int oe = __shfl_xor_sync(0xffffffffu, be, off);
                float oo = __shfl_xor_sync(0xffffffffu, bo, off);
                if (ov > bv2 || (ov == bv2 && oe < be)) { bv2 = ov; be = oe; bo = oo; }
            }
            wsel[k] = bo;
            esel[k] = be;
            if ((be & 31) == lane) {
                int bslot = be >> 5;
                #pragma unroll
                for (int s = 0; s < NGRP; s++)
                    if (s == bslot) mv[s] = -INFINITY;
            }
        }

        float tot = 0.0f;
        #pragma unroll
        for (int k = 0; k < TOPK; k++) tot += wsel[k];
        float inv = RSCALE / tot;

        const int gt = m0 + t;
        #pragma unroll
        for (int k = 0; k < TOPK; k++) {
            if (lane == k) {
                out[(size_t)gt * TOPK + k] = wsel[k] * inv;
                if (with_idx)
                    out[(size_t)N * TOPK + (size_t)gt * TOPK + k] = (float)esel[k];
            }
        }
    }
}

// ---------------------------------------------------------------------------
extern "C" void kernel_launch(void* const* d_in, const int* in_sizes, int n_in,
                              void* d_out, int out_size)
{
    const float* x    = (const float*)d_in[0];
    const float* w    = (const float*)d_in[1];
    const float* bias = (const float*)d_in[2];
    float* out = (float*)d_out;

    int N = in_sizes[0] / HID;
    int with_idx = (out_size >= 2 * N * TOPK) ? 1 : 0;

    cudaFuncSetAttribute(gate_fused_kernel,
                         cudaFuncAttributeMaxDynamicSharedMemorySize, SMEM_TOTAL);
    gate_fused_kernel<<<N / MT, 512, SMEM_TOTAL>>>(x, w, bias, out, N, with_idx);
}

// round 8
// speedup vs baseline: 1.1482x; 1.1300x over previous
#include <cuda_runtime.h>
#include <math.h>
#include <stdint.h>

// ---------------- problem constants ----------------
#define HID 2048
#define NEXP 256
#define NGRP 8
#define TOPG 4
#define TOPK 8
#define RSCALE 2.5f
#define MT 64                  // tokens per CTA
#define KT 32                  // K per smem stage
#define NST (HID / KT)         // 64 stages

// ---------------- smem layout (raw fp32 tiles only) ----------------
// row stride 36 floats: bank = (4*row + col) & 31 -> conflict-free frag loads
#define RS 36
#define OFF_BIAS 0
#define OFF_TILES 1024
#define AOFF 0
#define BOFF (MT * RS * 4)                       // 9216
#define STAGE (MT * RS * 4 + NEXP * RS * 4)      // 46080
#define NBUF 3
#define SMEM_TOTAL (OFF_TILES + NBUF * STAGE)    // 139264
#define SC_STRIDE 260

#define MMA(d, a, b) asm volatile( \
    "mma.sync.aligned.m16n8k8.row.col.f32.tf32.tf32.f32 " \
    "{%0,%1,%2,%3},{%4,%5,%6,%7},{%8,%9},{%0,%1,%2,%3};" \
    : "+f"((d)[0]), "+f"((d)[1]), "+f"((d)[2]), "+f"((d)[3]) \
    : "r"((a)[0]), "r"((a)[1]), "r"((a)[2]), "r"((a)[3]), \
      "r"((b)[0]), "r"((b)[1]))

#define CPA(dst, src) asm volatile( \
    "cp.async.cg.shared.global [%0], [%1], 16;" :: "r"(dst), "l"(src) : "memory")
#define CPA_COMMIT asm volatile("cp.async.commit_group;" ::: "memory")

static __device__ __forceinline__ uint32_t s2u(const void* p) {
    uint32_t r;
    asm("{ .reg .u64 t; cvta.to.shared.u64 t, %1; cvt.u32.u64 %0, t; }" : "=r"(r) : "l"(p));
    return r;
}

// truncation split in registers: hi = v & ~0x1FFF (bits HMMA keeps),
// lo = v - hi (exact fp32). 1 LOP3 + 1 FSUB, independent per element.
static __device__ __forceinline__ void tsplit(float v, uint32_t& h, uint32_t& l) {
    h = __float_as_uint(v) & 0xFFFFE000u;
    l = __float_as_uint(v - __uint_as_float(h));
}

// ---------------------------------------------------------------------------
// Fused: 3xTF32 mma.sync GEMM (64 x 256 x 2048 per CTA), dual accumulators,
// register-resident splits, 32x64 warp tiles, one barrier per stage,
// 3-buffer cp.async + sigmoid + grouped top-k routing. 256 threads, 8 warps.
// ---------------------------------------------------------------------------
extern "C" __global__ void __launch_bounds__(256, 1)
gate_fused_kernel(const float* __restrict__ x,
                  const float* __restrict__ w,
                  const float* __restrict__ bias,
                  float* __restrict__ out, int N, int with_idx)
{
    extern __shared__ __align__(1024) char smem[];
    const uint32_t sb = s2u(smem);
    const int tid  = threadIdx.x;
    const int wid  = tid >> 5;
    const int lane = tid & 31;
    const int m0   = blockIdx.x * MT;
    const int wm   = wid & 1;      // 2 M-groups of 32 tokens
    const int wn   = wid >> 1;     // 4 N-groups of 64 experts

    float* bs = (float*)(smem + OFF_BIAS);
    if (tid < NEXP) bs[tid] = bias[tid];

    float accH[2][8][4], accL[2][8][4];
    #pragma unroll
    for (int i = 0; i < 2; i++)
        #pragma unroll
        for (int j = 0; j < 8; j++)
            #pragma unroll
            for (int c = 0; c < 4; c++) { accH[i][j][c] = 0.0f; accL[i][j][c] = 0.0f; }

    const int lrow = tid >> 3;       // 0..31
    const int lq   = tid & 7;

    // ---- async load of raw fp32 tiles for stage s (buffer s % 3) ----
    auto ldga = [&](int s) {
        const int k0 = s * KT;
        const uint32_t bufa = sb + OFF_TILES + (s % NBUF) * STAGE;
        #pragma unroll
        for (int i = 0; i < 2; i++) {          // A: 64 rows
            int row = lrow + i * 32;
            uint32_t dst = bufa + AOFF + (uint32_t)(row * RS + lq * 4) * 4;
            CPA(dst, x + (size_t)(m0 + row) * HID + k0 + lq * 4);
        }
        #pragma unroll
        for (int i = 0; i < 8; i++) {          // B: 256 rows
            int row = lrow + i * 32;
            uint32_t dst = bufa + BOFF + (uint32_t)(row * RS + lq * 4) * 4;
            CPA(dst, w + (size_t)row * HID + k0 + lq * 4);
        }
        CPA_COMMIT;
    };

    const int afo = (wm * 32 + (lane >> 2)) * RS + (lane & 3);
    const int bfo = (wn * 64 + (lane >> 2)) * RS + (lane & 3);

    auto compute = [&](int s) {
        const char* buf = smem + OFF_TILES + (s % NBUF) * STAGE;
        const float* Ar = (const float*)(buf + AOFF);
        const float* Br = (const float*)(buf + BOFF);
        #pragma unroll
        for (int ks = 0; ks < 4; ks++) {
            const int kb = ks * 8;
            // A frags: raw LDS then register split
            uint32_t ah[2][4], al[2][4];
            #pragma unroll
            for (int mi = 0; mi < 2; mi++) {
                int o = afo + mi * (16 * RS) + kb;
                tsplit(Ar[o],              ah[mi][0], al[mi][0]);
                tsplit(Ar[o + 8 * RS],     ah[mi][1], al[mi][1]);
                tsplit(Ar[o + 4],          ah[mi][2], al[mi][2]);
                tsplit(Ar[o + 8 * RS + 4], ah[mi][3], al[mi][3]);
            }
            // B frags: raw LDS then register split (8 n8-blocks = 64 experts)
            uint32_t bh[8][2], bl[8][2];
            #pragma unroll
            for (int ni = 0; ni < 8; ni++) {
                int o = bfo + ni * (8 * RS) + kb;
                tsplit(Br[o],     bh[ni][0], bl[ni][0]);
                tsplit(Br[o + 4], bh[ni][1], bl[ni][1]);
            }
            // term-major: 16 MMAs between same-accumulator reuse
            #pragma unroll
            for (int ni = 0; ni < 8; ni++)
                #pragma unroll
                for (int mi = 0; mi < 2; mi++)
                    MMA(accH[mi][ni], ah[mi], bh[ni]);   // exact hi*hi
            #pragma unroll
            for (int ni = 0; ni < 8; ni++)
                #pragma unroll
                for (int mi = 0; mi < 2; mi++)
                    MMA(accL[mi][ni], al[mi], bh[ni]);
            #pragma unroll
            for (int ni = 0; ni < 8; ni++)
                #pragma unroll
                for (int mi = 0; mi < 2; mi++)
                    MMA(accL[mi][ni], ah[mi], bl[ni]);
        }
    };

    // ---- pipelined main loop: ONE barrier per stage ----
    ldga(0); ldga(1);
    for (int s = 0; s < NST; s++) {
        if (s + 1 < NST) {
            asm volatile("cp.async.wait_group 1;" ::: "memory");
        } else {
            asm volatile("cp.async.wait_group 0;" ::: "memory");
        }
        __syncthreads();                 // buf[s] ready; compute(s-1) finished
        if (s + 2 < NST) ldga(s + 2);    // buf[(s+2)%3] dead since stage s-1
        compute(s);
    }
    __syncthreads();   // tiles dead; reuse smem for scores overlay

    // ---- epilogue: combine acc, +bias, sigmoid, scores overlay ----
    float* sc = (float*)(smem + OFF_TILES);
    #pragma unroll
    for (int mi = 0; mi < 2; mi++) {
        int tr = wm * 32 + mi * 16 + (lane >> 2);
        #pragma unroll
        for (int ni = 0; ni < 8; ni++) {
            int e = wn * 64 + ni * 8 + (lane & 3) * 2;
            float s0 = (accH[mi][ni][0] + accL[mi][ni][0]) + bs[e];
            float s1 = (accH[mi][ni][1] + accL[mi][ni][1]) + bs[e + 1];
            float s2 = (accH[mi][ni][2] + accL[mi][ni][2]) + bs[e];
            float s3 = (accH[mi][ni][3] + accL[mi][ni][3]) + bs[e + 1];
            float2 v0, v1;
            v0.x = 1.0f / (1.0f + expf(-s0));
            v0.y = 1.0f / (1.0f + expf(-s1));
            v1.x = 1.0f / (1.0f + expf(-s2));
            v1.y = 1.0f / (1.0f + expf(-s3));
            *(float2*)&sc[tr * SC_STRIDE + e]       = v0;
            *(float2*)&sc[(tr + 8) * SC_STRIDE + e] = v1;
        }
    }
    __syncthreads();

    // ---- routing: warp per token, 8 tokens per warp ----
    for (int it = 0; it < 8; it++) {
        const int t = wid * 8 + it;
        const float* row = sc + t * SC_STRIDE;

        float orig[NGRP], rsc[NGRP];
        #pragma unroll
        for (int s = 0; s < NGRP; s++) {
            float sg = row[s * 32 + lane];
            orig[s] = sg;
            rsc[s] = sg + bs[s * 32 + lane];
        }

        // group score = top-2 sum (ties -> lower expert index)
        float gs[NGRP];
        #pragma unroll
        for (int g = 0; g < NGRP; g++) {
            float m1 = rsc[g];
            int l1 = lane;
            #pragma unroll
            for (int off = 16; off >= 1; off >>= 1) {
                float ov = __shfl_xor_sync(0xffffffffu, m1, off);
                int ol = __shfl_xor_sync(0xffffffffu, l1, off);
                if (ov > m1 || (ov == m1 && ol < l1)) { m1 = ov; l1 = ol; }
            }
            float v2 = (lane == l1) ? -INFINITY : rsc[g];
            #pragma unroll
            for (int off = 16; off >= 1; off >>= 1)
                v2 = fmaxf(v2, __shfl_xor_sync(0xffffffffu, v2, off));
            gs[g] = m1 + v2;
        }

        // keep top-4 groups (ties -> lower group index)
        float mv[NGRP];
        #pragma unroll
        for (int g = 0; g < NGRP; g++) {
            int cnt = 0;
            #pragma unroll
            for (int h = 0; h < NGRP; h++)
                cnt += (gs[h] > gs[g]) || (gs[h] == gs[g] && h < g);
            mv[g] = (cnt < TOPG) ? rsc[g] : -INFINITY;
        }

        // iterative top-8 (ties -> lower expert index)
        float wsel[TOPK];
        int esel[TOPK];
        #pragma unroll
        for (int k = 0; k < TOPK; k++) {
            float bv2 = -INFINITY; int be = NEXP; float bo = 0.0f;
            #pragma unroll
            for (int s = 0; s < NGRP; s++)
                if (mv[s] > bv2) { bv2 = mv[s]; be = s * 32 + lane; bo = orig[s]; }
            #pragma unroll
            for (int off = 16; off >= 1; off >>= 1) {
                float ov = __shfl_xor_sync(0xffffffffu, bv2, off);
                int oe = __shfl_xor_sync(0xffffffffu, be, off);
                float oo = __shfl_xor_sync(0xffffffffu, bo, off);
                if (ov > bv2 || (ov == bv2 && oe < be)) { bv2 = ov; be = oe; bo = oo; }
            }
            wsel[k] = bo;
            esel[k] = be;
            if ((be & 31) == lane) {
                int bslot = be >> 5;
                #pragma unroll
                for (int s = 0; s < NGRP; s++)
                    if (s == bslot) mv[s] = -INFINITY;
            }
        }

        float tot = 0.0f;
        #pragma unroll
        for (int k = 0; k < TOPK; k++) tot += wsel[k];
        float inv = RSCALE / tot;

        const int gt = m0 + t;
        #pragma unroll
        for (int k = 0; k < TOPK; k++) {
            if (lane == k) {
                out[(size_t)gt * TOPK + k] = wsel[k] * inv;
                if (with_idx)
                    out[(size_t)N * TOPK + (size_t)gt * TOPK + k] = (float)esel[k];
            }
        }
    }
}

// ---------------------------------------------------------------------------
extern "C" void kernel_launch(void* const* d_in, const int* in_sizes, int n_in,
                              void* d_out, int out_size)
{
    const float* x    = (const float*)d_in[0];
    const float* w    = (const float*)d_in[1];
    const float* bias = (const float*)d_in[2];
    float* out = (float*)d_out;

    int N = in_sizes[0] / HID;
    int with_idx = (out_size >= 2 * N * TOPK) ? 1 : 0;

    cudaFuncSetAttribute(gate_fused_kernel,
                         cudaFuncAttributeMaxDynamicSharedMemorySize, SMEM_TOTAL);
    gate_fused_kernel<<<N / MT, 256, SMEM_TOTAL>>>(x, w, bias, out, N, with_idx);
}

// round 9
// speedup vs baseline: 1.2361x; 1.0766x over previous
#include <cuda_runtime.h>
#include <cuda_fp16.h>
#include <math.h>
#include <stdint.h>

// ---------------- problem constants ----------------
#define HID 2048
#define NEXP 256
#define NGRP 8
#define TOPG 4
#define TOPK 8
#define RSCALE 2.5f
#define MT 64                  // tokens per CTA
#define KT 32                  // K per smem stage
#define NST (HID / KT)         // 64 stages
#define LSC 2048.0f            // lo-term scale (2^11), exact
#define ILSC (1.0f / 2048.0f)

// ---------------- smem layout ----------------
// raw fp32 tiles: rows 0..63 = A(tokens), 64..319 = B(experts); stride 36 floats
#define RSRAW 36
// packed fp16 tiles: per row 16 pairs, words [2p]=hi f16x2, [2p+1]=lo f16x2; stride 40 words
#define RSPK 40
#define OFF_BIAS 0
#define OFF_RAW 1024
#define RAWSTAGE (320 * RSRAW * 4)               // 46080
#define OFF_PK (OFF_RAW + 2 * RAWSTAGE)          // 93184
#define PKSTAGE (320 * RSPK * 4)                 // 51200
#define SMEM_TOTAL (OFF_PK + 2 * PKSTAGE)        // 195584
#define SC_STRIDE 260

#define MMA16(d, a, b) asm volatile( \
    "mma.sync.aligned.m16n8k16.row.col.f32.f16.f16.f32 " \
    "{%0,%1,%2,%3},{%4,%5,%6,%7},{%8,%9},{%0,%1,%2,%3};" \
    : "+f"((d)[0]), "+f"((d)[1]), "+f"((d)[2]), "+f"((d)[3]) \
    : "r"((a)[0]), "r"((a)[1]), "r"((a)[2]), "r"((a)[3]), \
      "r"((b)[0]), "r"((b)[1]))

#define CPA(dst, src) asm volatile( \
    "cp.async.cg.shared.global [%0], [%1], 16;" :: "r"(dst), "l"(src) : "memory")
#define CPA_COMMIT asm volatile("cp.async.commit_group;" ::: "memory")

static __device__ __forceinline__ uint32_t s2u(const void* p) {
    uint32_t r;
    asm("{ .reg .u64 t; cvta.to.shared.u64 t, %1; cvt.u32.u64 %0, t; }" : "=r"(r) : "l"(p));
    return r;
}

// ---------------------------------------------------------------------------
// Fused: 3-term fp16 mma.sync GEMM (64 x 256 x 2048 per CTA), dual fp32
// accumulators (exact hi*hi in accH; scaled cross terms in accL), split-once
// in smem, 2-buffer cp.async + sigmoid + grouped top-k routing.
// 512 threads, 16 warps, 32x32 warp tiles.
// ---------------------------------------------------------------------------
extern "C" __global__ void __launch_bounds__(512, 1)
gate_fused_kernel(const float* __restrict__ x,
                  const float* __restrict__ w,
                  const float* __restrict__ bias,
                  float* __restrict__ out, int N, int with_idx)
{
    extern __shared__ __align__(1024) char smem[];
    const uint32_t sb = s2u(smem);
    const int tid  = threadIdx.x;
    const int wid  = tid >> 5;
    const int lane = tid & 31;
    const int m0   = blockIdx.x * MT;
    const int wm   = wid & 1;      // 2 M-groups of 32 tokens
    const int wn   = wid >> 1;     // 8 N-groups of 32 experts

    float* bs = (float*)(smem + OFF_BIAS);
    if (tid < NEXP) bs[tid] = bias[tid];

    float accH[2][4][4], accL[2][4][4];
    #pragma unroll
    for (int i = 0; i < 2; i++)
        #pragma unroll
        for (int j = 0; j < 4; j++)
            #pragma unroll
            for (int c = 0; c < 4; c++) { accH[i][j][c] = 0.0f; accL[i][j][c] = 0.0f; }

    // ---- cp.async raw fp32 tiles (rows 0-63 = A, 64-319 = B) ----
    auto ldga = [&](int s) {
        const int k0 = s * KT;
        const uint32_t bufa = sb + OFF_RAW + (s & 1) * RAWSTAGE;
        #pragma unroll
        for (int i = 0; i < 5; i++) {
            int id = tid + i * 512;            // 2560 float4 total
            int row = id >> 3, q = id & 7;
            uint32_t dst = bufa + (uint32_t)(row * RSRAW + q * 4) * 4;
            const float* src = (row < MT)
                ? (x + (size_t)(m0 + row) * HID + k0 + q * 4)
                : (w + (size_t)(row - MT) * HID + k0 + q * 4);
            CPA(dst, src);
        }
        CPA_COMMIT;
    };

    // ---- split pass: raw fp32 -> interleaved {hi,lo} fp16x2, once/element ----
    auto splitp = [&](int s) {
        const float* raw = (const float*)(smem + OFF_RAW + (s & 1) * RAWSTAGE);
        uint32_t* pk = (uint32_t*)(smem + OFF_PK + (s & 1) * PKSTAGE);
        #pragma unroll
        for (int i = 0; i < 10; i++) {
            int pid = tid + i * 512;           // 5120 pairs total
            int row = pid >> 4, p = pid & 15;
            float2 v = *(const float2*)(raw + row * RSRAW + 2 * p);
            __half2 h2 = __floats2half2_rn(v.x, v.y);
            float2 hf = __half22float2(h2);
            __half2 l2 = __floats2half2_rn((v.x - hf.x) * LSC, (v.y - hf.y) * LSC);
            uint2 wv;
            wv.x = *(uint32_t*)&h2;
            wv.y = *(uint32_t*)&l2;
            *(uint2*)(pk + row * RSPK + 2 * p) = wv;
        }
    };

    auto compute = [&](int s) {
        const uint32_t* pk = (const uint32_t*)(smem + OFF_PK + (s & 1) * PKSTAGE);
        #pragma unroll
        for (int c = 0; c < 2; c++) {          // two k16 chunks per stage
            const int pbase = (c * 8 + (lane & 3)) * 2;
            uint32_t ah[2][4], al[2][4];
            #pragma unroll
            for (int mi = 0; mi < 2; mi++) {
                int r = wm * 32 + mi * 16 + (lane >> 2);
                int o = r * RSPK + pbase;
                uint2 w0 = *(const uint2*)(pk + o);
                uint2 w1 = *(const uint2*)(pk + o + 8 * RSPK);
                uint2 w2 = *(const uint2*)(pk + o + 8);
                uint2 w3 = *(const uint2*)(pk + o + 8 * RSPK + 8);
                ah[mi][0] = w0.x; al[mi][0] = w0.y;
                ah[mi][1] = w1.x; al[mi][1] = w1.y;
                ah[mi][2] = w2.x; al[mi][2] = w2.y;
                ah[mi][3] = w3.x; al[mi][3] = w3.y;
            }
            #pragma unroll
            for (int np = 0; np < 2; np++) {   // pairs of n8 tiles
                uint32_t bh[2][2], bl[2][2];
                #pragma unroll
                for (int j = 0; j < 2; j++) {
                    int e = wn * 32 + (np * 2 + j) * 8 + (lane >> 2);
                    int o = (MT + e) * RSPK + pbase;
                    uint2 u0 = *(const uint2*)(pk + o);
                    uint2 u1 = *(const uint2*)(pk + o + 8);
                    bh[j][0] = u0.x; bl[j][0] = u0.y;
                    bh[j][1] = u1.x; bl[j][1] = u1.y;
                }
                // term-major: 4 MMAs between same-accumulator reuse
                #pragma unroll
                for (int mi = 0; mi < 2; mi++)
                    #pragma unroll
                    for (int j = 0; j < 2; j++)
                        MMA16(accH[mi][np * 2 + j], ah[mi], bh[j]);   // exact hi*hi
                #pragma unroll
                for (int mi = 0; mi < 2; mi++)
                    #pragma unroll
                    for (int j = 0; j < 2; j++)
                        MMA16(accL[mi][np * 2 + j], al[mi], bh[j]);
                #pragma unroll
                for (int mi = 0; mi < 2; mi++)
                    #pragma unroll
                    for (int j = 0; j < 2; j++)
                        MMA16(accL[mi][np * 2 + j], ah[mi], bl[j]);
            }
        }
    };

    // ---- pipelined main loop ----
    ldga(0);
    for (int s = 0; s < NST; s++) {
        asm volatile("cp.async.wait_group 0;" ::: "memory");
        __syncthreads();                 // raw(s) landed; split(s-1)/compute(s-1) done
        if (s + 1 < NST) ldga(s + 1);    // raw((s+1)&1): split(s-1) finished with it
        splitp(s);                       // pk(s&1): compute(s-2) finished with it
        __syncthreads();
        compute(s);
    }
    __syncthreads();   // tiles dead; reuse smem for scores overlay

    // ---- epilogue: combine acc (unscale lo), +bias, sigmoid, overlay ----
    float* sc = (float*)(smem + OFF_RAW);
    #pragma unroll
    for (int mi = 0; mi < 2; mi++) {
        int tr = wm * 32 + mi * 16 + (lane >> 2);
        #pragma unroll
        for (int ni = 0; ni < 4; ni++) {
            int e = wn * 32 + ni * 8 + (lane & 3) * 2;
            float s0 = fmaf(accL[mi][ni][0], ILSC, accH[mi][ni][0]) + bs[e];
            float s1 = fmaf(accL[mi][ni][1], ILSC, accH[mi][ni][1]) + bs[e + 1];
            float s2 = fmaf(accL[mi][ni][2], ILSC, accH[mi][ni][2]) + bs[e];
            float s3 = fmaf(accL[mi][ni][3], ILSC, accH[mi][ni][3]) + bs[e + 1];
            float2 v0, v1;
            v0.x = 1.0f / (1.0f + expf(-s0));
            v0.y = 1.0f / (1.0f + expf(-s1));
            v1.x = 1.0f / (1.0f + expf(-s2));
            v1.y = 1.0f / (1.0f + expf(-s3));
            *(float2*)&sc[tr * SC_STRIDE + e]       = v0;
            *(float2*)&sc[(tr + 8) * SC_STRIDE + e] = v1;
        }
    }
    __syncthreads();

    // ---- routing: warp per token, 4 tokens per warp ----
    for (int it = 0; it < 4; it++) {
        const int t = wid * 4 + it;
        const float* row = sc + t * SC_STRIDE;

        float orig[NGRP], rsc[NGRP];
        #pragma unroll
        for (int s = 0; s < NGRP; s++) {
            float sg = row[s * 32 + lane];
            orig[s] = sg;
            rsc[s] = sg + bs[s * 32 + lane];
        }

        // group score = top-2 sum (ties -> lower expert index)
        float gs[NGRP];
        #pragma unroll
        for (int g = 0; g < NGRP; g++) {
            float m1 = rsc[g];
            int l1 = lane;
            #pragma unroll
            for (int off = 16; off >= 1; off >>= 1) {
                float ov = __shfl_xor_sync(0xffffffffu, m1, off);
                int ol = __shfl_xor_sync(0xffffffffu, l1, off);
                if (ov > m1 || (ov == m1 && ol < l1)) { m1 = ov; l1 = ol; }
            }
            float v2 = (lane == l1) ? -INFINITY : rsc[g];
            #pragma unroll
            for (int off = 16; off >= 1; off >>= 1)
                v2 = fmaxf(v2, __shfl_xor_sync(0xffffffffu, v2, off));
            gs[g] = m1 + v2;
        }

        // keep top-4 groups (ties -> lower group index)
        float mv[NGRP];
        #pragma unroll
        for (int g = 0; g < NGRP; g++) {
            int cnt = 0;
            #pragma unroll
            for (int h = 0; h < NGRP; h++)
                cnt += (gs[h] > gs[g]) || (gs[h] == gs[g] && h < g);
            mv[g] = (cnt < TOPG) ? rsc[g] : -INFINITY;
        }

        // iterative top-8 (ties -> lower expert index)
        float wsel[TOPK];
        int esel[TOPK];
        #pragma unroll
        for (int k = 0; k < TOPK; k++) {
            float bv2 = -INFINITY; int be = NEXP; float bo = 0.0f;
            #pragma unroll
            for (int s = 0; s < NGRP; s++)
                if (mv[s] > bv2) { bv2 = mv[s]; be = s * 32 + lane; bo = orig[s]; }
            #pragma unroll
            for (int off = 16; off >= 1; off >>= 1) {
                float ov = __shfl_xor_sync(0xffffffffu, bv2, off);
                int oe = __shfl_xor_sync(0xffffffffu, be, off);
                float oo = __shfl_xor_sync(0xffffffffu, bo, off);
                if (ov > bv2 || (ov == bv2 && oe < be)) { bv2 = ov; be = oe; bo = oo; }
            }
            wsel[k] = bo;
            esel[k] = be;
            if ((be & 31) == lane) {
                int bslot = be >> 5;
                #pragma unroll
                for (int s = 0; s < NGRP; s++)
                    if (s == bslot) mv[s] = -INFINITY;
            }
        }

        float tot = 0.0f;
        #pragma unroll
        for (int k = 0; k < TOPK; k++) tot += wsel[k];
        float inv = RSCALE / tot;

        const int gt = m0 + t;
        #pragma unroll
        for (int k = 0; k < TOPK; k++) {
            if (lane == k) {
                out[(size_t)gt * TOPK + k] = wsel[k] * inv;
                if (with_idx)
                    out[(size_t)N * TOPK + (size_t)gt * TOPK + k] = (float)esel[k];
            }
        }
    }
}

// ---------------------------------------------------------------------------
extern "C" void kernel_launch(void* const* d_in, const int* in_sizes, int n_in,
                              void* d_out, int out_size)
{
    const float* x    = (const float*)d_in[0];
    const float* w    = (const float*)d_in[1];
    const float* bias = (const float*)d_in[2];
    float* out = (float*)d_out;

    int N = in_sizes[0] / HID;
    int with_idx = (out_size >= 2 * N * TOPK) ? 1 : 0;

    cudaFuncSetAttribute(gate_fused_kernel,
                         cudaFuncAttributeMaxDynamicSharedMemorySize, SMEM_TOTAL);
    gate_fused_kernel<<<N / MT, 512, SMEM_TOTAL>>>(x, w, bias, out, N, with_idx);
}

// round 10
// speedup vs baseline: 1.2905x; 1.0440x over previous
#include <cuda_runtime.h>
#include <cuda_fp16.h>
#include <math.h>
#include <stdint.h>

// ---------------- problem constants ----------------
#define HID 2048
#define NEXP 256
#define NGRP 8
#define TOPG 4
#define TOPK 8
#define RSCALE 2.5f
#define MT 64                  // tokens per CTA
#define KT 32                  // K per smem stage
#define NST (HID / KT)         // 64 stages
#define LSC 2048.0f            // lo-term scale (2^11), exact
#define ILSC (1.0f / 2048.0f)

// ---------------- packed fp16 smem layout ----------------
// per row 16 pairs; words [2p]=hi f16x2, [2p+1]=lo f16x2; stride 40 words.
// rows 0..63 = A (tokens), rows 64..319 = B (experts).
#define RSPK 40
#define OFF_BIAS 0
#define OFF_PK 1024
#define PKSTAGE (320 * RSPK * 4)                 // 51200
#define SMEM_TOTAL (OFF_PK + 2 * PKSTAGE)        // 103424
#define SC_STRIDE 260

// W pre-split: [256 rows][1024 pairs] of uint2 {hi16x2, lo16x2} = 2 MB
__device__ uint2 g_wpk[NEXP * (HID / 2)];

#define MMA16(d, a, b) asm volatile( \
    "mma.sync.aligned.m16n8k16.row.col.f32.f16.f16.f32 " \
    "{%0,%1,%2,%3},{%4,%5,%6,%7},{%8,%9},{%0,%1,%2,%3};" \
    : "+f"((d)[0]), "+f"((d)[1]), "+f"((d)[2]), "+f"((d)[3]) \
    : "r"((a)[0]), "r"((a)[1]), "r"((a)[2]), "r"((a)[3]), \
      "r"((b)[0]), "r"((b)[1]))

#define CPA(dst, src) asm volatile( \
    "cp.async.cg.shared.global [%0], [%1], 16;" :: "r"(dst), "l"(src) : "memory")
#define CPA_COMMIT asm volatile("cp.async.commit_group;" ::: "memory")

static __device__ __forceinline__ uint32_t s2u(const void* p) {
    uint32_t r;
    asm("{ .reg .u64 t; cvta.to.shared.u64 t, %1; cvt.u32.u64 %0, t; }" : "=r"(r) : "l"(p));
    return r;
}
static __device__ __forceinline__ uint32_t h2u(__half2 h) {
    return *(uint32_t*)&h;
}

// split 2 floats -> {hi f16x2, lo f16x2} (lo scaled by 2^11, exact unscale later)
static __device__ __forceinline__ uint2 packpair(float a, float b) {
    __half2 h = __floats2half2_rn(a, b);
    float2 f = __half22float2(h);
    __half2 l = __floats2half2_rn((a - f.x) * LSC, (b - f.y) * LSC);
    uint2 r; r.x = h2u(h); r.y = h2u(l);
    return r;
}

// ---------------------------------------------------------------------------
// One-time W split: fp32 [256,2048] -> interleaved {hi,lo} fp16x2 pairs.
// ---------------------------------------------------------------------------
extern "C" __global__ void split_w_kernel(const float* __restrict__ w,
                                          uint2* __restrict__ wpk)
{
    int id = blockIdx.x * 512 + threadIdx.x;        // 131072 float4s
    float4 v = ((const float4*)w)[id];
    wpk[id * 2 + 0] = packpair(v.x, v.y);
    wpk[id * 2 + 1] = packpair(v.z, v.w);
}

// ---------------------------------------------------------------------------
// Fused: 3-term fp16 mma.sync GEMM (64 x 256 x 2048 per CTA), dual fp32
// accumulators, B pre-split in gmem (cp.async packed), A split in registers,
// ONE barrier per stage + sigmoid + grouped top-k routing.
// 512 threads, 16 warps, 32x32 warp tiles.
// ---------------------------------------------------------------------------
extern "C" __global__ void __launch_bounds__(512, 1)
gate_fused_kernel(const float* __restrict__ x,
                  const uint2* __restrict__ wpk,
                  const float* __restrict__ bias,
                  float* __restrict__ out, int N, int with_idx)
{
    extern __shared__ __align__(1024) char smem[];
    const uint32_t sb = s2u(smem);
    const int tid  = threadIdx.x;
    const int wid  = tid >> 5;
    const int lane = tid & 31;
    const int m0   = blockIdx.x * MT;
    const int wm   = wid & 1;      // 2 M-groups of 32 tokens
    const int wn   = wid >> 1;     // 8 N-groups of 32 experts

    float* bs = (float*)(smem + OFF_BIAS);
    if (tid < NEXP) bs[tid] = bias[tid];

    float accH[2][4][4], accL[2][4][4];
    #pragma unroll
    for (int i = 0; i < 2; i++)
        #pragma unroll
        for (int j = 0; j < 4; j++)
            #pragma unroll
            for (int c = 0; c < 4; c++) { accH[i][j][c] = 0.0f; accL[i][j][c] = 0.0f; }

    const int arow = tid >> 3;     // 0..63 (A row)
    const int achk = tid & 7;      // float4 chunk within 32-float k-slab

    // ---- A: one float4 per thread per stage ----
    auto ldgA = [&](int s) {
        return *(const float4*)(x + (size_t)(m0 + arow) * HID + s * KT + achk * 4);
    };
    // ---- A: register split -> packed STS (words: hi,lo,hi,lo) ----
    auto stsA = [&](int s, float4 v) {
        uint32_t* pk = (uint32_t*)(smem + OFF_PK + (s & 1) * PKSTAGE);
        uint2 p0 = packpair(v.x, v.y);
        uint2 p1 = packpair(v.z, v.w);
        uint4 o4; o4.x = p0.x; o4.y = p0.y; o4.z = p1.x; o4.w = p1.y;
        *(uint4*)(pk + arow * RSPK + achk * 4) = o4;
    };
    // ---- B: cp.async packed tile (256 rows x 16 pairs) ----
    auto cpaB = [&](int s) {
        const uint32_t bufa = sb + OFF_PK + (s & 1) * PKSTAGE;
        #pragma unroll
        for (int i = 0; i < 4; i++) {
            int id = tid + i * 512;            // 2048 16B-chunks
            int row = id >> 3, c = id & 7;
            uint32_t dst = bufa + (uint32_t)((MT + row) * RSPK + c * 4) * 4;
            CPA(dst, wpk + (size_t)row * (HID / 2) + s * 16 + 2 * c);
        }
        CPA_COMMIT;
    };

    auto compute = [&](int s) {
        const uint32_t* pk = (const uint32_t*)(smem + OFF_PK + (s & 1) * PKSTAGE);
        #pragma unroll
        for (int c = 0; c < 2; c++) {          // two k16 chunks per stage
            const int pbase = (c * 8 + (lane & 3)) * 2;
            uint32_t ah[2][4], al[2][4];
            #pragma unroll
            for (int mi = 0; mi < 2; mi++) {
                int r = wm * 32 + mi * 16 + (lane >> 2);
                int o = r * RSPK + pbase;
                uint2 w0 = *(const uint2*)(pk + o);
                uint2 w1 = *(const uint2*)(pk + o + 8 * RSPK);
                uint2 w2 = *(const uint2*)(pk + o + 8);
                uint2 w3 = *(const uint2*)(pk + o + 8 * RSPK + 8);
                ah[mi][0] = w0.x; al[mi][0] = w0.y;
                ah[mi][1] = w1.x; al[mi][1] = w1.y;
                ah[mi][2] = w2.x; al[mi][2] = w2.y;
                ah[mi][3] = w3.x; al[mi][3] = w3.y;
            }
            #pragma unroll
            for (int np = 0; np < 2; np++) {   // pairs of n8 tiles
                uint32_t bh[2][2], bl[2][2];
                #pragma unroll
                for (int j = 0; j < 2; j++) {
                    int e = wn * 32 + (np * 2 + j) * 8 + (lane >> 2);
                    int o = (MT + e) * RSPK + pbase;
                    uint2 u0 = *(const uint2*)(pk + o);
                    uint2 u1 = *(const uint2*)(pk + o + 8);
                    bh[j][0] = u0.x; bl[j][0] = u0.y;
                    bh[j][1] = u1.x; bl[j][1] = u1.y;
                }
                #pragma unroll
                for (int mi = 0; mi < 2; mi++)
                    #pragma unroll
                    for (int j = 0; j < 2; j++)
                        MMA16(accH[mi][np * 2 + j], ah[mi], bh[j]);   // exact hi*hi
                #pragma unroll
                for (int mi = 0; mi < 2; mi++)
                    #pragma unroll
                    for (int j = 0; j < 2; j++)
                        MMA16(accL[mi][np * 2 + j], al[mi], bh[j]);
                #pragma unroll
                for (int mi = 0; mi < 2; mi++)
                    #pragma unroll
                    for (int j = 0; j < 2; j++)
                        MMA16(accL[mi][np * 2 + j], ah[mi], bl[j]);
            }
        }
    };

    // ---- pipelined main loop: ONE barrier per stage ----
    float4 avA = ldgA(0);
    float4 avB = ldgA(1);
    cpaB(0);
    stsA(0, avA);
    for (int s = 0; s < NST; s++) {
        asm volatile("cp.async.wait_group 0;" ::: "memory");
        __syncthreads();     // B(s) visible; A(s) STS visible; compute(s-1) done
        if (s + 1 < NST) {
            cpaB(s + 1);                          // buf[(s+1)&1]: compute(s-1) done with it
            stsA(s + 1, (s & 1) ? avA : avB);     // same buffer, A region
            if (s + 2 < NST) {
                if (s & 1) avB = ldgA(s + 2);
                else       avA = ldgA(s + 2);
            }
        }
        compute(s);
    }
    __syncthreads();   // tiles dead; reuse smem for scores overlay

    // ---- epilogue: combine acc (unscale lo), +bias, sigmoid, overlay ----
    float* sc = (float*)(smem + OFF_PK);
    #pragma unroll
    for (int mi = 0; mi < 2; mi++) {
        int tr = wm * 32 + mi * 16 + (lane >> 2);
        #pragma unroll
        for (int ni = 0; ni < 4; ni++) {
            int e = wn * 32 + ni * 8 + (lane & 3) * 2;
            float s0 = fmaf(accL[mi][ni][0], ILSC, accH[mi][ni][0]) + bs[e];
            float s1 = fmaf(accL[mi][ni][1], ILSC, accH[mi][ni][1]) + bs[e + 1];
            float s2 = fmaf(accL[mi][ni][2], ILSC, accH[mi][ni][2]) + bs[e];
            float s3 = fmaf(accL[mi][ni][3], ILSC, accH[mi][ni][3]) + bs[e + 1];
            float2 v0, v1;
            v0.x = 1.0f / (1.0f + expf(-s0));
            v0.y = 1.0f / (1.0f + expf(-s1));
            v1.x = 1.0f / (1.0f + expf(-s2));
            v1.y = 1.0f / (1.0f + expf(-s3));
            *(float2*)&sc[tr * SC_STRIDE + e]       = v0;
            *(float2*)&sc[(tr + 8) * SC_STRIDE + e] = v1;
        }
    }
    __syncthreads();

    // ---- routing: warp per token, 4 tokens per warp ----
    for (int it = 0; it < 4; it++) {
        const int t = wid * 4 + it;
        const float* row = sc + t * SC_STRIDE;

        float orig[NGRP], rsc[NGRP];
        #pragma unroll
        for (int s = 0; s < NGRP; s++) {
            float sg = row[s * 32 + lane];
            orig[s] = sg;
            rsc[s] = sg + bs[s * 32 + lane];
        }

        // group score = top-2 sum (ties -> lower expert index)
        float gs[NGRP];
        #pragma unroll
        for (int g = 0; g < NGRP; g++) {
            float m1 = rsc[g];
            int l1 = lane;
            #pragma unroll
            for (int off = 16; off >= 1; off >>= 1) {
                float ov = __shfl_xor_sync(0xffffffffu, m1, off);
                int ol = __shfl_xor_sync(0xffffffffu, l1, off);
                if (ov > m1 || (ov == m1 && ol < l1)) { m1 = ov; l1 = ol; }
            }
            float v2 = (lane == l1) ? -INFINITY : rsc[g];
            #pragma unroll
            for (int off = 16; off >= 1; off >>= 1)
                v2 = fmaxf(v2, __shfl_xor_sync(0xffffffffu, v2, off));
            gs[g] = m1 + v2;
        }

        // keep top-4 groups (ties -> lower group index)
        float mv[NGRP];
        #pragma unroll
        for (int g = 0; g < NGRP; g++) {
            int cnt = 0;
            #pragma unroll
            for (int h = 0; h < NGRP; h++)
                cnt += (gs[h] > gs[g]) || (gs[h] == gs[g] && h < g);
            mv[g] = (cnt < TOPG) ? rsc[g] : -INFINITY;
        }

        // iterative top-8 (ties -> lower expert index)
        float wsel[TOPK];
        int esel[TOPK];
        #pragma unroll
        for (int k = 0; k < TOPK; k++) {
            float bv2 = -INFINITY; int be = NEXP; float bo = 0.0f;
            #pragma unroll
            for (int s = 0; s < NGRP; s++)
                if (mv[s] > bv2) { bv2 = mv[s]; be = s * 32 + lane; bo = orig[s]; }
            #pragma unroll
            for (int off = 16; off >= 1; off >>= 1) {
                float ov = __shfl_xor_sync(0xffffffffu, bv2, off);
                int oe = __shfl_xor_sync(0xffffffffu, be, off);
                float oo = __shfl_xor_sync(0xffffffffu, bo, off);
                if (ov > bv2 || (ov == bv2 && oe < be)) { bv2 = ov; be = oe; bo = oo; }
            }
            wsel[k] = bo;
            esel[k] = be;
            if ((be & 31) == lane) {
                int bslot = be >> 5;
                #pragma unroll
                for (int s = 0; s < NGRP; s++)
                    if (s == bslot) mv[s] = -INFINITY;
            }
        }

        float tot = 0.0f;
        #pragma unroll
        for (int k = 0; k < TOPK; k++) tot += wsel[k];
        float inv = RSCALE / tot;

        const int gt = m0 + t;
        #pragma unroll
        for (int k = 0; k < TOPK; k++) {
            if (lane == k) {
                out[(size_t)gt * TOPK + k] = wsel[k] * inv;
                if (with_idx)
                    out[(size_t)N * TOPK + (size_t)gt * TOPK + k] = (float)esel[k];
            }
        }
    }
}

// ---------------------------------------------------------------------------
extern "C" void kernel_launch(void* const* d_in, const int* in_sizes, int n_in,
                              void* d_out, int out_size)
{
    const float* x    = (const float*)d_in[0];
    const float* w    = (const float*)d_in[1];
    const float* bias = (const float*)d_in[2];
    float* out = (float*)d_out;

    int N = in_sizes[0] / HID;
    int with_idx = (out_size >= 2 * N * TOPK) ? 1 : 0;

    uint2* wpk = nullptr;
    cudaGetSymbolAddress((void**)&wpk, g_wpk);

    split_w_kernel<<<NEXP * HID / 4 / 512, 512>>>(w, wpk);

    cudaFuncSetAttribute(gate_fused_kernel,
                         cudaFuncAttributeMaxDynamicSharedMemorySize, SMEM_TOTAL);
    gate_fused_kernel<<<N / MT, 512, SMEM_TOTAL>>>(x, wpk, bias, out, N, with_idx);
}

// round 11
// speedup vs baseline: 1.6359x; 1.2676x over previous
#include <cuda_runtime.h>
#include <cuda_fp16.h>
#include <math.h>
#include <stdint.h>

// ---------------- problem constants ----------------
#define HID 2048
#define NEXP 256
#define NGRP 8
#define TOPG 4
#define TOPK 8
#define RSCALE 2.5f
#define MT 64                  // tokens per CTA
#define KT 64                  // K per smem stage (doubled)
#define NST (HID / KT)         // 32 stages
#define LSC 2048.0f            // lo-term scale (2^11), exact
#define ILSC (1.0f / 2048.0f)

// ---------------- packed fp16 smem layout ----------------
// per row 32 pairs; words [2p]=hi f16x2, [2p+1]=lo f16x2; stride 72 words.
// rows 0..63 = A (tokens), rows 64..319 = B (experts).
#define RSPK 72
#define OFF_BIAS 0
#define OFF_PK 1024
#define PKSTAGE (320 * RSPK * 4)                 // 92160
#define SMEM_TOTAL (OFF_PK + 2 * PKSTAGE)        // 185344
#define SC_STRIDE 260

// W pre-split: [256 rows][1024 pairs] of uint2 {hi16x2, lo16x2} = 2 MB
__device__ uint2 g_wpk[NEXP * (HID / 2)];

#define MMA16(d, a, b) asm volatile( \
    "mma.sync.aligned.m16n8k16.row.col.f32.f16.f16.f32 " \
    "{%0,%1,%2,%3},{%4,%5,%6,%7},{%8,%9},{%0,%1,%2,%3};" \
    : "+f"((d)[0]), "+f"((d)[1]), "+f"((d)[2]), "+f"((d)[3]) \
    : "r"((a)[0]), "r"((a)[1]), "r"((a)[2]), "r"((a)[3]), \
      "r"((b)[0]), "r"((b)[1]))

#define CPA(dst, src) asm volatile( \
    "cp.async.cg.shared.global [%0], [%1], 16;" :: "r"(dst), "l"(src) : "memory")
#define CPA_COMMIT asm volatile("cp.async.commit_group;" ::: "memory")

static __device__ __forceinline__ uint32_t s2u(const void* p) {
    uint32_t r;
    asm("{ .reg .u64 t; cvta.to.shared.u64 t, %1; cvt.u32.u64 %0, t; }" : "=r"(r) : "l"(p));
    return r;
}
static __device__ __forceinline__ uint32_t h2u(__half2 h) {
    return *(uint32_t*)&h;
}

// split 2 floats -> {hi f16x2, lo f16x2} (lo scaled by 2^11, exact unscale later)
static __device__ __forceinline__ uint2 packpair(float a, float b) {
    __half2 h = __floats2half2_rn(a, b);
    float2 f = __half22float2(h);
    __half2 l = __floats2half2_rn((a - f.x) * LSC, (b - f.y) * LSC);
    uint2 r; r.x = h2u(h); r.y = h2u(l);
    return r;
}

// ---------------------------------------------------------------------------
// One-time W split: fp32 [256,2048] -> interleaved {hi,lo} fp16x2 pairs.
// ---------------------------------------------------------------------------
extern "C" __global__ void split_w_kernel(const float* __restrict__ w,
                                          uint2* __restrict__ wpk)
{
    int id = blockIdx.x * 512 + threadIdx.x;        // 131072 float4s
    float4 v = ((const float4*)w)[id];
    wpk[id * 2 + 0] = packpair(v.x, v.y);
    wpk[id * 2 + 1] = packpair(v.z, v.w);
}

// ---------------------------------------------------------------------------
// Fused: 3-term fp16 mma.sync GEMM (64 x 256 x 2048 per CTA), dual fp32
// accumulators, B pre-split (cp.async packed), A split in registers,
// KT=64 stages (one barrier per 64-K) + sigmoid + grouped top-k routing.
// 512 threads, 16 warps, 32x32 warp tiles.
// ---------------------------------------------------------------------------
extern "C" __global__ void __launch_bounds__(512, 1)
gate_fused_kernel(const float* __restrict__ x,
                  const uint2* __restrict__ wpk,
                  const float* __restrict__ bias,
                  float* __restrict__ out, int N, int with_idx)
{
    extern __shared__ __align__(1024) char smem[];
    const uint32_t sb = s2u(smem);
    const int tid  = threadIdx.x;
    const int wid  = tid >> 5;
    const int lane = tid & 31;
    const int m0   = blockIdx.x * MT;
    const int wm   = wid & 1;      // 2 M-groups of 32 tokens
    const int wn   = wid >> 1;     // 8 N-groups of 32 experts

    float* bs = (float*)(smem + OFF_BIAS);
    if (tid < NEXP) bs[tid] = bias[tid];

    float accH[2][4][4], accL[2][4][4];
    #pragma unroll
    for (int i = 0; i < 2; i++)
        #pragma unroll
        for (int j = 0; j < 4; j++)
            #pragma unroll
            for (int c = 0; c < 4; c++) { accH[i][j][c] = 0.0f; accL[i][j][c] = 0.0f; }

    const int arow = tid >> 3;     // 0..63 (A row)
    const int achk = tid & 7;      // float4 chunk 0..7 (covers chunks achk, achk+8)

    float4 avA, avB;               // A prefetch: 2 float4 per thread per stage

    auto ldgA = [&](int s) {
        const float* p = x + (size_t)(m0 + arow) * HID + s * KT + achk * 4;
        avA = *(const float4*)p;
        avB = *(const float4*)(p + 32);
    };
    // A: register split -> packed STS (two uint4 per thread)
    auto stsA = [&](int s) {
        uint32_t* pk = (uint32_t*)(smem + OFF_PK + (s & 1) * PKSTAGE);
        uint2 p0 = packpair(avA.x, avA.y);
        uint2 p1 = packpair(avA.z, avA.w);
        uint4 o4a; o4a.x = p0.x; o4a.y = p0.y; o4a.z = p1.x; o4a.w = p1.y;
        *(uint4*)(pk + arow * RSPK + achk * 4) = o4a;
        uint2 p2 = packpair(avB.x, avB.y);
        uint2 p3 = packpair(avB.z, avB.w);
        uint4 o4b; o4b.x = p2.x; o4b.y = p2.y; o4b.z = p3.x; o4b.w = p3.y;
        *(uint4*)(pk + arow * RSPK + achk * 4 + 32) = o4b;
    };
    // B: cp.async packed tile (256 rows x 32 pairs = 64KB)
    auto cpaB = [&](int s) {
        const uint32_t bufa = sb + OFF_PK + (s & 1) * PKSTAGE;
        #pragma unroll
        for (int i = 0; i < 8; i++) {
            int id = tid + i * 512;            // 4096 16B-chunks
            int row = id >> 4, c = id & 15;
            uint32_t dst = bufa + (uint32_t)((MT + row) * RSPK + c * 4) * 4;
            CPA(dst, wpk + (size_t)row * (HID / 2) + s * 32 + 2 * c);
        }
        CPA_COMMIT;
    };

    auto compute = [&](int s) {
        const uint32_t* pk = (const uint32_t*)(smem + OFF_PK + (s & 1) * PKSTAGE);
        #pragma unroll
        for (int c = 0; c < 4; c++) {          // four k16 chunks per stage
            const int pbase = (c * 8 + (lane & 3)) * 2;
            uint32_t ah[2][4], al[2][4];
            #pragma unroll
            for (int mi = 0; mi < 2; mi++) {
                int r = wm * 32 + mi * 16 + (lane >> 2);
                int o = r * RSPK + pbase;
                uint2 w0 = *(const uint2*)(pk + o);
                uint2 w1 = *(const uint2*)(pk + o + 8 * RSPK);
                uint2 w2 = *(const uint2*)(pk + o + 8);
                uint2 w3 = *(const uint2*)(pk + o + 8 * RSPK + 8);
                ah[mi][0] = w0.x; al[mi][0] = w0.y;
                ah[mi][1] = w1.x; al[mi][1] = w1.y;
                ah[mi][2] = w2.x; al[mi][2] = w2.y;
                ah[mi][3] = w3.x; al[mi][3] = w3.y;
            }
            #pragma unroll
            for (int np = 0; np < 2; np++) {   // pairs of n8 tiles
                uint32_t bh[2][2], bl[2][2];
                #pragma unroll
                for (int j = 0; j < 2; j++) {
                    int e = wn * 32 + (np * 2 + j) * 8 + (lane >> 2);
                    int o = (MT + e) * RSPK + pbase;
                    uint2 u0 = *(const uint2*)(pk + o);
                    uint2 u1 = *(const uint2*)(pk + o + 8);
                    bh[j][0] = u0.x; bl[j][0] = u0.y;
                    bh[j][1] = u1.x; bl[j][1] = u1.y;
                }
                #pragma unroll
                for (int mi = 0; mi < 2; mi++)
                    #pragma unroll
                    for (int j = 0; j < 2; j++)
                        MMA16(accH[mi][np * 2 + j], ah[mi], bh[j]);   // exact hi*hi
                #pragma unroll
                for (int mi = 0; mi < 2; mi++)
                    #pragma unroll
                    for (int j = 0; j < 2; j++)
                        MMA16(accL[mi][np * 2 + j], al[mi], bh[j]);
                #pragma unroll
                for (int mi = 0; mi < 2; mi++)
                    #pragma unroll
                    for (int j = 0; j < 2; j++)
                        MMA16(accL[mi][np * 2 + j], ah[mi], bl[j]);
            }
        }
    };

    // ---- pipelined main loop: ONE barrier per 64-K stage ----
    cpaB(0);
    ldgA(0);
    stsA(0);
    ldgA(1);
    for (int s = 0; s < NST; s++) {
        asm volatile("cp.async.wait_group 0;" ::: "memory");
        __syncthreads();     // B(s) visible; A(s) STS visible; compute(s-1) done
        if (s + 1 < NST) {
            cpaB(s + 1);                 // buf[(s+1)&1]: compute(s-1) done with it
            stsA(s + 1);                 // A region of same buffer
            if (s + 2 < NST) ldgA(s + 2);
        }
        compute(s);
    }
    __syncthreads();   // tiles dead; reuse smem for scores overlay

    // ---- epilogue: combine acc (unscale lo), +bias, sigmoid, overlay ----
    float* sc = (float*)(smem + OFF_PK);
    #pragma unroll
    for (int mi = 0; mi < 2; mi++) {
        int tr = wm * 32 + mi * 16 + (lane >> 2);
        #pragma unroll
        for (int ni = 0; ni < 4; ni++) {
            int e = wn * 32 + ni * 8 + (lane & 3) * 2;
            float s0 = fmaf(accL[mi][ni][0], ILSC, accH[mi][ni][0]) + bs[e];
            float s1 = fmaf(accL[mi][ni][1], ILSC, accH[mi][ni][1]) + bs[e + 1];
            float s2 = fmaf(accL[mi][ni][2], ILSC, accH[mi][ni][2]) + bs[e];
            float s3 = fmaf(accL[mi][ni][3], ILSC, accH[mi][ni][3]) + bs[e + 1];
            float2 v0, v1;
            v0.x = 1.0f / (1.0f + expf(-s0));
            v0.y = 1.0f / (1.0f + expf(-s1));
            v1.x = 1.0f / (1.0f + expf(-s2));
            v1.y = 1.0f / (1.0f + expf(-s3));
            *(float2*)&sc[tr * SC_STRIDE + e]       = v0;
            *(float2*)&sc[(tr + 8) * SC_STRIDE + e] = v1;
        }
    }
    __syncthreads();

    // ---- routing: warp per token, 4 tokens per warp ----
    for (int it = 0; it < 4; it++) {
        const int t = wid * 4 + it;
        const float* row = sc + t * SC_STRIDE;

        float orig[NGRP], rsc[NGRP];
        #pragma unroll
        for (int s = 0; s < NGRP; s++) {
            float sg = row[s * 32 + lane];
            orig[s] = sg;
            rsc[s] = sg + bs[s * 32 + lane];
        }

        // group score = top-2 sum (ties -> lower expert index)
        float gs[NGRP];
        #pragma unroll
        for (int g = 0; g < NGRP; g++) {
            float m1 = rsc[g];
            int l1 = lane;
            #pragma unroll
            for (int off = 16; off >= 1; off >>= 1) {
                float ov = __shfl_xor_sync(0xffffffffu, m1, off);
                int ol = __shfl_xor_sync(0xffffffffu, l1, off);
                if (ov > m1 || (ov == m1 && ol < l1)) { m1 = ov; l1 = ol; }
            }
            float v2 = (lane == l1) ? -INFINITY : rsc[g];
            #pragma unroll
            for (int off = 16; off >= 1; off >>= 1)
                v2 = fmaxf(v2, __shfl_xor_sync(0xffffffffu, v2, off));
            gs[g] = m1 + v2;
        }

        // keep top-4 groups (ties -> lower group index)
        float mv[NGRP];
        #pragma unroll
        for (int g = 0; g < NGRP; g++) {
            int cnt = 0;
            #pragma unroll
            for (int h = 0; h < NGRP; h++)
                cnt += (gs[h] > gs[g]) || (gs[h] == gs[g] && h < g);
            mv[g] = (cnt < TOPG) ? rsc[g] : -INFINITY;
        }

        // iterative top-8 (ties -> lower expert index)
        float wsel[TOPK];
        int esel[TOPK];
        #pragma unroll
        for (int k = 0; k < TOPK; k++) {
            float bv2 = -INFINITY; int be = NEXP; float bo = 0.0f;
            #pragma unroll
            for (int s = 0; s < NGRP; s++)
                if (mv[s] > bv2) { bv2 = mv[s]; be = s * 32 + lane; bo = orig[s]; }
            #pragma unroll
            for (int off = 16; off >= 1; off >>= 1) {
                float ov = __shfl_xor_sync(0xffffffffu, bv2, off);
                int oe = __shfl_xor_sync(0xffffffffu, be, off);
                float oo = __shfl_xor_sync(0xffffffffu, bo, off);
                if (ov > bv2 || (ov == bv2 && oe < be)) { bv2 = ov; be = oe; bo = oo; }
            }
            wsel[k] = bo;
            esel[k] = be;
            if ((be & 31) == lane) {
                int bslot = be >> 5;
                #pragma unroll
                for (int s = 0; s < NGRP; s++)
                    if (s == bslot) mv[s] = -INFINITY;
            }
        }

        float tot = 0.0f;
        #pragma unroll
        for (int k = 0; k < TOPK; k++) tot += wsel[k];
        float inv = RSCALE / tot;

        const int gt = m0 + t;
        #pragma unroll
        for (int k = 0; k < TOPK; k++) {
            if (lane == k) {
                out[(size_t)gt * TOPK + k] = wsel[k] * inv;
                if (with_idx)
                    out[(size_t)N * TOPK + (size_t)gt * TOPK + k] = (float)esel[k];
            }
        }
    }
}

// ---------------------------------------------------------------------------
extern "C" void kernel_launch(void* const* d_in, const int* in_sizes, int n_in,
                              void* d_out, int out_size)
{
    const float* x    = (const float*)d_in[0];
    const float* w    = (const float*)d_in[1];
    const float* bias = (const float*)d_in[2];
    float* out = (float*)d_out;

    int N = in_sizes[0] / HID;
    int with_idx = (out_size >= 2 * N * TOPK) ? 1 : 0;

    uint2* wpk = nullptr;
    cudaGetSymbolAddress((void**)&wpk, g_wpk);

    split_w_kernel<<<NEXP * HID / 4 / 512, 512>>>(w, wpk);

    cudaFuncSetAttribute(gate_fused_kernel,
                         cudaFuncAttributeMaxDynamicSharedMemorySize, SMEM_TOTAL);
    gate_fused_kernel<<<N / MT, 512, SMEM_TOTAL>>>(x, wpk, bias, out, N, with_idx);
}